// round 16
// baseline (speedup 1.0000x reference)
#include <cuda_runtime.h>
#include <cstdint>

#define N_PLANES 73
#define BOARD 8
#define FLAT (N_PLANES * BOARD * BOARD)   // 4672
#define N_MOVES 1858
#define IDX_PAD 1872                      // u16 count, 3744 B (16B multiple)
#define IDX_BYTES (IDX_PAD * 2)           // 3744
#define BATCH 4096
#define ROWS 2                            // batch rows per gather block
#define OUT4 ((ROWS * N_MOVES) / 4)       // 929 float4 stores per block
#define PAIR_BYTES (ROWS * FLAT * 4)      // 37376

#define W_BYTES ((long)FLAT * N_MOVES * 4)        // 34,722,304
#define CHUNK_BYTES 32768                          // W chunk per extract block
#define CHUNK_F4 (CHUNK_BYTES / 16)                // 2048
#define E_BLOCKS ((int)((W_BYTES + CHUNK_BYTES - 1) / CHUNK_BYTES))  // 1060

// Scratch (device mallocs banned): one-hot row index per move, as u16.
__device__ __align__(16) unsigned short g_idx16[IDX_PAD];

// ----------------------------- PTX helpers ---------------------------------
__device__ __forceinline__ uint32_t smem_u32(const void* p) {
    uint32_t a;
    asm("{ .reg .u64 t; cvta.to.shared.u64 t, %1; cvt.u32.u64 %0, t; }"
        : "=r"(a) : "l"(p));
    return a;
}
__device__ __forceinline__ void mbar_init(uint32_t mbar, uint32_t cnt) {
    asm volatile("mbarrier.init.shared.b64 [%0], %1;" :: "r"(mbar), "r"(cnt));
}
__device__ __forceinline__ void mbar_expect_tx(uint32_t mbar, uint32_t bytes) {
    asm volatile("mbarrier.arrive.expect_tx.shared.b64 _, [%0], %1;"
                 :: "r"(mbar), "r"(bytes));
}
// evict_last 1.0: pin W (34.7 MB) in L2 across graph replays. Proven in R12.
__device__ __forceinline__ void bulk_g2s_keep(uint32_t dst, const void* src,
                                              uint32_t bytes, uint32_t mbar) {
    uint64_t pol;
    asm volatile("createpolicy.fractional.L2::evict_last.b64 %0, 1.0;" : "=l"(pol));
    asm volatile(
        "cp.async.bulk.shared::cta.global.mbarrier::complete_tx::bytes.L2::cache_hint "
        "[%0], [%1], %2, [%3], %4;"
        :: "r"(dst), "l"(src), "r"(bytes), "r"(mbar), "l"(pol) : "memory");
}
// evict_last 0.5 (single-token form; remainder defaults to evict_unchanged):
// pin ~half of x (~38 MB) without oversubscribing the evict_last pool
// (R13 lesson: pinning all of x evicts W).
__device__ __forceinline__ void bulk_g2s_half(uint32_t dst, const void* src,
                                              uint32_t bytes, uint32_t mbar) {
    uint64_t pol;
    asm volatile("createpolicy.fractional.L2::evict_last.b64 %0, 0.5;" : "=l"(pol));
    asm volatile(
        "cp.async.bulk.shared::cta.global.mbarrier::complete_tx::bytes.L2::cache_hint "
        "[%0], [%1], %2, [%3], %4;"
        :: "r"(dst), "l"(src), "r"(bytes), "r"(mbar), "l"(pol) : "memory");
}
__device__ __forceinline__ void bulk_g2s(uint32_t dst, const void* src,
                                         uint32_t bytes, uint32_t mbar) {
    asm volatile(
        "cp.async.bulk.shared::cta.global.mbarrier::complete_tx::bytes "
        "[%0], [%1], %2, [%3];"
        :: "r"(dst), "l"(src), "r"(bytes), "r"(mbar) : "memory");
}
__device__ __forceinline__ void mbar_wait(uint32_t mbar, uint32_t parity) {
    asm volatile(
        "{\n\t"
        ".reg .pred P;\n\t"
        "WAIT_%=:\n\t"
        "mbarrier.try_wait.parity.acquire.cta.shared::cta.b64 P, [%0], %1, 0x989680;\n\t"
        "@P bra.uni DONE_%=;\n\t"
        "bra.uni WAIT_%=;\n\t"
        "DONE_%=:\n\t"
        "}"
        :: "r"(mbar), "r"(parity) : "memory");
}

// ---------------------------------------------------------------------------
// Kernel 1: recover idx16[j] = r with W[r][j] == 1.0.
// TMA-copies 32KB W chunks into smem with L2::evict_last so W stays
// L2-resident across graph replays; steady-state replays serve it from L2.
// ---------------------------------------------------------------------------
__global__ __launch_bounds__(256)
void extract_idx_kernel(const char* __restrict__ W,
                        unsigned short* __restrict__ idx16) {
    __shared__ __align__(16) float4 buf[CHUNK_F4];   // 32768 B
    __shared__ __align__(8)  unsigned long long mbar;

    const int tid = threadIdx.x;
    const long off = (long)blockIdx.x * CHUNK_BYTES;
    const uint32_t bytes =
        (uint32_t)((W_BYTES - off < CHUNK_BYTES) ? (W_BYTES - off) : CHUNK_BYTES);
    const uint32_t mb = smem_u32(&mbar);

    if (tid == 0) mbar_init(mb, 1);
    __syncthreads();
    if (tid == 0) {
        mbar_expect_tx(mb, bytes);
        bulk_g2s_keep(smem_u32(buf), W + off, bytes, mb);
    }
    mbar_wait(mb, 0);

    const int nf4 = bytes / 16;
    const int ebase = (int)(off / 4);                // element offset of chunk
    #pragma unroll
    for (int i = tid; i < CHUNK_F4; i += 256) {
        if (i >= nf4) break;
        float4 v = buf[i];
        if (v.x != 0.f || v.y != 0.f || v.z != 0.f || v.w != 0.f) {
            int e = ebase + 4 * i;
            if (v.x != 0.f) { int t = e;     idx16[t % N_MOVES] = (unsigned short)(t / N_MOVES); }
            if (v.y != 0.f) { int t = e + 1; idx16[t % N_MOVES] = (unsigned short)(t / N_MOVES); }
            if (v.z != 0.f) { int t = e + 2; idx16[t % N_MOVES] = (unsigned short)(t / N_MOVES); }
            if (v.w != 0.f) { int t = e + 3; idx16[t % N_MOVES] = (unsigned short)(t / N_MOVES); }
        }
    }
}

// ---------------------------------------------------------------------------
// Kernel 2: each block gathers ROWS=2 consecutive batch rows.
// x staged via TMA with evict_last fraction 0.5 — ~half of x becomes
// L2-replay-resident without displacing W. Store phase: branchless float4
// streaming stores, all operands from smem.
// ---------------------------------------------------------------------------
__global__ __launch_bounds__(256)
void gather_kernel(const float* __restrict__ x,
                   float* __restrict__ out) {
    __shared__ __align__(16) float rows[ROWS * FLAT];        // 37376 B
    __shared__ __align__(16) unsigned short sidx[IDX_PAD];   // 3744 B
    __shared__ __align__(8)  unsigned long long mbar;

    const int tid = threadIdx.x;
    const size_t b0 = (size_t)blockIdx.x * ROWS;
    const uint32_t mb = smem_u32(&mbar);

    if (tid == 0) mbar_init(mb, 1);
    __syncthreads();
    if (tid == 0) {
        mbar_expect_tx(mb, PAIR_BYTES + IDX_BYTES);
        bulk_g2s_half(smem_u32(rows), x + b0 * FLAT, PAIR_BYTES, mb);
        bulk_g2s(smem_u32(sidx), g_idx16, IDX_BYTES, mb);
    }
    mbar_wait(mb, 0);

    // 929 float4 streaming stores per block (~3.6 per thread); block's out
    // span is 16B-aligned (2*1858*4 = 14864 ≡ 0 mod 16).
    float4* ob4 = (float4*)(out + b0 * N_MOVES);
    #pragma unroll
    for (int j = tid; j < OUT4; j += 256) {
        int e0 = 4 * j;
        float v[4];
        #pragma unroll
        for (int k = 0; k < 4; k++) {
            int e = e0 + k;
            int r = (e >= N_MOVES) ? 1 : 0;      // row within the pair
            int c = e - r * N_MOVES;
            v[k] = rows[r * FLAT + sidx[c]];
        }
        __stcs(&ob4[j], make_float4(v[0], v[1], v[2], v[3]));
    }
}

extern "C" void kernel_launch(void* const* d_in, const int* in_sizes, int n_in,
                              void* d_out, int out_size) {
    const float* x = (const float*)d_in[0];          // [4096, 73, 8, 8]
    const float* W = (const float*)d_in[1];          // [4672, 1858]
    float* out = (float*)d_out;                      // [4096, 1858]

    unsigned short* idx_ptr;
    cudaGetSymbolAddress((void**)&idx_ptr, g_idx16);

    extract_idx_kernel<<<E_BLOCKS, 256>>>((const char*)W, idx_ptr);
    gather_kernel<<<BATCH / ROWS, 256>>>(x, out);
}

// round 17
// speedup vs baseline: 1.2879x; 1.2879x over previous
#include <cuda_runtime.h>
#include <cstdint>

#define N_PLANES 73
#define BOARD 8
#define FLAT (N_PLANES * BOARD * BOARD)   // 4672
#define N_MOVES 1858
#define IDX_PAD 1872                      // u16 count, 3744 B (16B multiple)
#define IDX_BYTES (IDX_PAD * 2)           // 3744
#define BATCH 4096
#define ROWS 2                            // batch rows per gather block
#define OUT4 ((ROWS * N_MOVES) / 4)       // 929 float4 stores per block
#define PAIR_BYTES (ROWS * FLAT * 4)      // 37376

#define W_BYTES ((long)FLAT * N_MOVES * 4)        // 34,722,304
#define CHUNK_BYTES 32768                          // W chunk per extract block
#define CHUNK_F4 (CHUNK_BYTES / 16)                // 2048
#define E_BLOCKS ((int)((W_BYTES + CHUNK_BYTES - 1) / CHUNK_BYTES))  // 1060

// Scratch (device mallocs banned): one-hot row index per move, as u16.
__device__ __align__(16) unsigned short g_idx16[IDX_PAD];

// ----------------------------- PTX helpers ---------------------------------
__device__ __forceinline__ uint32_t smem_u32(const void* p) {
    uint32_t a;
    asm("{ .reg .u64 t; cvta.to.shared.u64 t, %1; cvt.u32.u64 %0, t; }"
        : "=r"(a) : "l"(p));
    return a;
}
__device__ __forceinline__ void mbar_init(uint32_t mbar, uint32_t cnt) {
    asm volatile("mbarrier.init.shared.b64 [%0], %1;" :: "r"(mbar), "r"(cnt));
}
__device__ __forceinline__ void mbar_expect_tx(uint32_t mbar, uint32_t bytes) {
    asm volatile("mbarrier.arrive.expect_tx.shared.b64 _, [%0], %1;"
                 :: "r"(mbar), "r"(bytes));
}
// evict_last: keep src cached in L2 across graph replays (for W only —
// R13/R16 showed tagging x as well displaces W and regresses).
__device__ __forceinline__ void bulk_g2s_keep(uint32_t dst, const void* src,
                                              uint32_t bytes, uint32_t mbar) {
    uint64_t pol;
    asm volatile("createpolicy.fractional.L2::evict_last.b64 %0, 1.0;" : "=l"(pol));
    asm volatile(
        "cp.async.bulk.shared::cta.global.mbarrier::complete_tx::bytes.L2::cache_hint "
        "[%0], [%1], %2, [%3], %4;"
        :: "r"(dst), "l"(src), "r"(bytes), "r"(mbar), "l"(pol) : "memory");
}
// evict_first: streaming src, don't pollute L2 (for x)
__device__ __forceinline__ void bulk_g2s_stream(uint32_t dst, const void* src,
                                                uint32_t bytes, uint32_t mbar) {
    uint64_t pol;
    asm volatile("createpolicy.fractional.L2::evict_first.b64 %0, 1.0;" : "=l"(pol));
    asm volatile(
        "cp.async.bulk.shared::cta.global.mbarrier::complete_tx::bytes.L2::cache_hint "
        "[%0], [%1], %2, [%3], %4;"
        :: "r"(dst), "l"(src), "r"(bytes), "r"(mbar), "l"(pol) : "memory");
}
__device__ __forceinline__ void bulk_g2s(uint32_t dst, const void* src,
                                         uint32_t bytes, uint32_t mbar) {
    asm volatile(
        "cp.async.bulk.shared::cta.global.mbarrier::complete_tx::bytes "
        "[%0], [%1], %2, [%3];"
        :: "r"(dst), "l"(src), "r"(bytes), "r"(mbar) : "memory");
}
__device__ __forceinline__ void mbar_wait(uint32_t mbar, uint32_t parity) {
    asm volatile(
        "{\n\t"
        ".reg .pred P;\n\t"
        "WAIT_%=:\n\t"
        "mbarrier.try_wait.parity.acquire.cta.shared::cta.b64 P, [%0], %1, 0x989680;\n\t"
        "@P bra.uni DONE_%=;\n\t"
        "bra.uni WAIT_%=;\n\t"
        "DONE_%=:\n\t"
        "}"
        :: "r"(mbar), "r"(parity) : "memory");
}

// ---------------------------------------------------------------------------
// Kernel 1: recover idx16[j] = r with W[r][j] == 1.0.
// TMA-copies 32KB W chunks into smem with L2::evict_last so W (34.7 MB) stays
// L2-resident across graph replays; steady-state replays serve it from L2.
// ---------------------------------------------------------------------------
__global__ __launch_bounds__(256)
void extract_idx_kernel(const char* __restrict__ W,
                        unsigned short* __restrict__ idx16) {
    __shared__ __align__(16) float4 buf[CHUNK_F4];   // 32768 B
    __shared__ __align__(8)  unsigned long long mbar;

    const int tid = threadIdx.x;
    const long off = (long)blockIdx.x * CHUNK_BYTES;
    const uint32_t bytes =
        (uint32_t)((W_BYTES - off < CHUNK_BYTES) ? (W_BYTES - off) : CHUNK_BYTES);
    const uint32_t mb = smem_u32(&mbar);

    if (tid == 0) mbar_init(mb, 1);
    __syncthreads();
    if (tid == 0) {
        mbar_expect_tx(mb, bytes);
        bulk_g2s_keep(smem_u32(buf), W + off, bytes, mb);
    }
    mbar_wait(mb, 0);

    const int nf4 = bytes / 16;
    const int ebase = (int)(off / 4);                // element offset of chunk
    #pragma unroll
    for (int i = tid; i < CHUNK_F4; i += 256) {
        if (i >= nf4) break;
        float4 v = buf[i];
        if (v.x != 0.f || v.y != 0.f || v.z != 0.f || v.w != 0.f) {
            int e = ebase + 4 * i;
            if (v.x != 0.f) { int t = e;     idx16[t % N_MOVES] = (unsigned short)(t / N_MOVES); }
            if (v.y != 0.f) { int t = e + 1; idx16[t % N_MOVES] = (unsigned short)(t / N_MOVES); }
            if (v.z != 0.f) { int t = e + 2; idx16[t % N_MOVES] = (unsigned short)(t / N_MOVES); }
            if (v.w != 0.f) { int t = e + 3; idx16[t % N_MOVES] = (unsigned short)(t / N_MOVES); }
        }
    }
}

// ---------------------------------------------------------------------------
// Kernel 2: each block gathers ROWS=2 consecutive batch rows.
// x staged via TMA with L2::evict_first (pure stream, protects W's residency);
// idx table TMA'd with default policy (tiny, hot). Store phase: branchless
// float4 streaming stores, all operands from smem.
// ---------------------------------------------------------------------------
__global__ __launch_bounds__(256)
void gather_kernel(const float* __restrict__ x,
                   float* __restrict__ out) {
    __shared__ __align__(16) float rows[ROWS * FLAT];        // 37376 B
    __shared__ __align__(16) unsigned short sidx[IDX_PAD];   // 3744 B
    __shared__ __align__(8)  unsigned long long mbar;

    const int tid = threadIdx.x;
    const size_t b0 = (size_t)blockIdx.x * ROWS;
    const uint32_t mb = smem_u32(&mbar);

    if (tid == 0) mbar_init(mb, 1);
    __syncthreads();
    if (tid == 0) {
        mbar_expect_tx(mb, PAIR_BYTES + IDX_BYTES);
        bulk_g2s_stream(smem_u32(rows), x + b0 * FLAT, PAIR_BYTES, mb);
        bulk_g2s(smem_u32(sidx), g_idx16, IDX_BYTES, mb);
    }
    mbar_wait(mb, 0);

    // 929 float4 streaming stores per block (~3.6 per thread); block's out
    // span is 16B-aligned (2*1858*4 = 14864 ≡ 0 mod 16).
    float4* ob4 = (float4*)(out + b0 * N_MOVES);
    #pragma unroll
    for (int j = tid; j < OUT4; j += 256) {
        int e0 = 4 * j;
        float v[4];
        #pragma unroll
        for (int k = 0; k < 4; k++) {
            int e = e0 + k;
            int r = (e >= N_MOVES) ? 1 : 0;      // row within the pair
            int c = e - r * N_MOVES;
            v[k] = rows[r * FLAT + sidx[c]];
        }
        __stcs(&ob4[j], make_float4(v[0], v[1], v[2], v[3]));
    }
}

extern "C" void kernel_launch(void* const* d_in, const int* in_sizes, int n_in,
                              void* d_out, int out_size) {
    const float* x = (const float*)d_in[0];          // [4096, 73, 8, 8]
    const float* W = (const float*)d_in[1];          // [4672, 1858]
    float* out = (float*)d_out;                      // [4096, 1858]

    unsigned short* idx_ptr;
    cudaGetSymbolAddress((void**)&idx_ptr, g_idx16);

    extract_idx_kernel<<<E_BLOCKS, 256>>>((const char*)W, idx_ptr);
    gather_kernel<<<BATCH / ROWS, 256>>>(x, out);
}